// round 8
// baseline (speedup 1.0000x reference)
#include <cuda_runtime.h>

// Problem constants (fixed by the dataset)
#define Bn 16
#define Cn 128
#define Hn 64
#define Wn 64
#define Kn 16

// ---------------------------------------------------------------------------
// Compile-time: per-piece 4x4 matrices M[sr][m][j] = monomial coeff m (of u in
// [0,1]) of basis function alpha_{sr+j}'s polynomial on piece sr.
// ---------------------------------------------------------------------------
constexpr double kn_c(int i) {
    return i <= 3 ? -1.0 : (i >= 16 ? 1.0 : -1.0 + (double)(i - 3) * (2.0 / 13.0));
}

struct B4 { double n[4]; };

constexpr B4 basis_at(double tt, int sr) {
    const int span = sr + 3;
    double lft[4] = {0, 0, 0, 0}, rgt[4] = {0, 0, 0, 0}, Nb[4] = {1.0, 0, 0, 0};
    for (int j = 1; j <= 3; j++) {
        lft[j] = tt - kn_c(span + 1 - j);
        rgt[j] = kn_c(span + j) - tt;
        double saved = 0.0;
        for (int r = 0; r < j; r++) {
            double den = rgt[r + 1] + lft[j - r];
            double tmp = Nb[r] / den;
            Nb[r] = saved + rgt[r + 1] * tmp;
            saved = lft[j - r] * tmp;
        }
        Nb[j] = saved;
    }
    B4 b = {{Nb[0], Nb[1], Nb[2], Nb[3]}};
    return b;
}

struct Tab { float m[13][4][4]; };   // [piece][monomial power][alpha j]

constexpr Tab make_tab() {
    Tab T = {};
    const double h = 2.0 / 13.0;
    for (int sr = 0; sr < 13; sr++) {
        double t0 = -1.0 + (double)sr * h;
        for (int j = 0; j < 4; j++) {
            double y0 = basis_at(t0, sr).n[j];
            double y1 = basis_at(t0 + h / 3.0, sr).n[j];
            double y2 = basis_at(t0 + 2.0 * h / 3.0, sr).n[j];
            double y3 = basis_at(t0 + h, sr).n[j];
            double d0 = y0;
            double d1 = 3.0 * (y1 - y0);
            double d2 = 4.5 * (y2 - 2.0 * y1 + y0);
            double d3 = 4.5 * (y3 - 3.0 * y2 + 3.0 * y1 - y0);
            T.m[sr][0][j] = (float)d0;
            T.m[sr][1][j] = (float)(d1 - d2 / 3.0 + 2.0 * d3 / 9.0);
            T.m[sr][2][j] = (float)(d2 - d3);
            T.m[sr][3][j] = (float)d3;
        }
    }
    return T;
}

__constant__ Tab c_tab = make_tab();

// ---------------------------------------------------------------------------
// Per-element (all 4-cycle FMA/ALU ops in the dependent chain):
//   uf  = x*av2 + bv2
//   ufc = clamp(uf, 0, 13)
//   y   = fadd_rd(ufc, 2^23)   -> mantissa low bits = floor(ufc) = k0 in [0,13]
//   kf  = y - 2^23  ;  u = uf - kf
//   k   = (uf > 14) ? 14 : k0           (strict: uf==14 i.e. t==1 -> piece 12)
//   4 conflict-free LDS.32 + 3-FMA Horner; affine part folded into c0,c1.
// ---------------------------------------------------------------------------
__device__ __forceinline__ float eval_one(float x, float av2, float bv2,
                                          const float* tab) {
    const float MAGIC = 8388608.0f;            // 2^23
    float uf  = fmaf(x, av2, bv2);
    float ufc = fminf(fmaxf(uf, 0.0f), 13.0f);
    float y   = __fadd_rd(ufc, MAGIC);         // floor lives in mantissa
    int   k0  = __float_as_int(y) & 15;        // 0..13
    float kf  = y - MAGIC;                     // exact float floor
    float u   = uf - kf;
    int k = (uf > 14.0f) ? 14 : k0;
    float c0 = tab[k];
    float c1 = tab[16 + k];
    float c2 = tab[32 + k];
    float c3 = tab[48 + k];
    float p = fmaf(c3, u, c2);
    p = fmaf(p, u, c1);
    return fmaf(p, u, c0);
}

// ---------------------------------------------------------------------------
// grid = 8192 blocks (4 per (b,c) plane), block = 256, 1 float4 per thread.
// Low register demand -> full residency; many waves smooth barrier tails.
// ---------------------------------------------------------------------------
__global__ void __launch_bounds__(256)
kan_spline_fused(const float4* __restrict__ x,
                 const float*  __restrict__ a,
                 const float*  __restrict__ b,
                 const float*  __restrict__ alpha,
                 const float*  __restrict__ gain,
                 const float*  __restrict__ bias,
                 float4* __restrict__ out) {
    __shared__ float tab[64];              // [power*16 + k], conflict-free

    int bid = blockIdx.x;
    int c = (bid >> 2) & (Cn - 1);         // 4 blocks per plane
    int tid = threadIdx.x;

    if (tid < 15) {
        float av = a[c];
        float bv = b[c];
        float gv = gain[c];
        float bi = bias[c];
        // affine fold: gv*x + bi = g1*u + g0  with u = uf - keff
        float g1 = gv / (6.5f * av);
        float keff = (float)min(tid, 13);  // entry 14 uses u from kf=13
        float g0 = fmaf(g1, keff - 7.5f - 6.5f * bv, bi);

        float c0 = g0, c1 = g1, c2 = 0.0f, c3 = 0.0f;
        int sr = tid - 1;                  // -1..13 ; valid pieces 0..12
        if (sr >= 0 && sr <= 12) {
            float al0 = alpha[c * Kn + sr];
            float al1 = alpha[c * Kn + sr + 1];
            float al2 = alpha[c * Kn + sr + 2];
            float al3 = alpha[c * Kn + sr + 3];
            const float (*M)[4] = c_tab.m[sr];
            c0 += fmaf(M[0][0], al0, fmaf(M[0][1], al1, fmaf(M[0][2], al2, M[0][3] * al3)));
            c1 += fmaf(M[1][0], al0, fmaf(M[1][1], al1, fmaf(M[1][2], al2, M[1][3] * al3)));
            c2  = fmaf(M[2][0], al0, fmaf(M[2][1], al1, fmaf(M[2][2], al2, M[2][3] * al3)));
            c3  = fmaf(M[3][0], al0, fmaf(M[3][1], al1, fmaf(M[3][2], al2, M[3][3] * al3)));
        }
        tab[tid]      = c0;
        tab[16 + tid] = c1;
        tab[32 + tid] = c2;
        tab[48 + tid] = c3;
    }
    float av2 = 6.5f * __ldg(a + c);                 // uf = x*(6.5a) + (6.5b+7.5)
    float bv2 = fmaf(6.5f, __ldg(b + c), 7.5f);
    __syncthreads();

    int i = bid * 256 + tid;
    float4 xv = __ldg(x + i);
    float4 ov;
    ov.x = eval_one(xv.x, av2, bv2, tab);
    ov.y = eval_one(xv.y, av2, bv2, tab);
    ov.z = eval_one(xv.z, av2, bv2, tab);
    ov.w = eval_one(xv.w, av2, bv2, tab);
    out[i] = ov;
}

// ---------------------------------------------------------------------------
// Launch: d_in order = x, a, b, alpha, id_gain, bias
// ---------------------------------------------------------------------------
extern "C" void kernel_launch(void* const* d_in, const int* in_sizes, int n_in,
                              void* d_out, int out_size) {
    const float* x      = (const float*)d_in[0];
    const float* a      = (const float*)d_in[1];
    const float* b      = (const float*)d_in[2];
    const float* alpha  = (const float*)d_in[3];
    const float* gain   = (const float*)d_in[4];
    const float* bias   = (const float*)d_in[5];
    float* out = (float*)d_out;

    const int total4 = (Bn * Cn * Hn * Wn) / 4;   // 2,097,152 float4
    const int blocks = total4 / 256;              // 8192
    kan_spline_fused<<<blocks, 256>>>((const float4*)x, a, b, alpha, gain, bias,
                                      (float4*)out);
}

// round 9
// speedup vs baseline: 1.2718x; 1.2718x over previous
#include <cuda_runtime.h>

// Problem constants (fixed by the dataset)
#define Bn 16
#define Cn 128
#define Hn 64
#define Wn 64
#define Kn 16

// ---------------------------------------------------------------------------
// Compile-time: per-piece 4x4 matrices M[sr][m][j] = monomial coeff m (of u in
// [0,1]) of basis function alpha_{sr+j}'s polynomial on piece sr.
// ---------------------------------------------------------------------------
constexpr double kn_c(int i) {
    return i <= 3 ? -1.0 : (i >= 16 ? 1.0 : -1.0 + (double)(i - 3) * (2.0 / 13.0));
}

struct B4 { double n[4]; };

constexpr B4 basis_at(double tt, int sr) {
    const int span = sr + 3;
    double lft[4] = {0, 0, 0, 0}, rgt[4] = {0, 0, 0, 0}, Nb[4] = {1.0, 0, 0, 0};
    for (int j = 1; j <= 3; j++) {
        lft[j] = tt - kn_c(span + 1 - j);
        rgt[j] = kn_c(span + j) - tt;
        double saved = 0.0;
        for (int r = 0; r < j; r++) {
            double den = rgt[r + 1] + lft[j - r];
            double tmp = Nb[r] / den;
            Nb[r] = saved + rgt[r + 1] * tmp;
            saved = lft[j - r] * tmp;
        }
        Nb[j] = saved;
    }
    B4 b = {{Nb[0], Nb[1], Nb[2], Nb[3]}};
    return b;
}

struct Tab { float m[13][4][4]; };   // [piece][monomial power][alpha j]

constexpr Tab make_tab() {
    Tab T = {};
    const double h = 2.0 / 13.0;
    for (int sr = 0; sr < 13; sr++) {
        double t0 = -1.0 + (double)sr * h;
        for (int j = 0; j < 4; j++) {
            double y0 = basis_at(t0, sr).n[j];
            double y1 = basis_at(t0 + h / 3.0, sr).n[j];
            double y2 = basis_at(t0 + 2.0 * h / 3.0, sr).n[j];
            double y3 = basis_at(t0 + h, sr).n[j];
            double d0 = y0;
            double d1 = 3.0 * (y1 - y0);
            double d2 = 4.5 * (y2 - 2.0 * y1 + y0);
            double d3 = 4.5 * (y3 - 3.0 * y2 + 3.0 * y1 - y0);
            T.m[sr][0][j] = (float)d0;
            T.m[sr][1][j] = (float)(d1 - d2 / 3.0 + 2.0 * d3 / 9.0);
            T.m[sr][2][j] = (float)(d2 - d3);
            T.m[sr][3][j] = (float)d3;
        }
    }
    return T;
}

__constant__ Tab c_tab = make_tab();

// ---------------------------------------------------------------------------
// Per-element (all 4-cycle FMA/ALU ops in the dependent chain):
//   uf  = x*av2 + bv2
//   ufc = clamp(uf, 0, 13)
//   y   = fadd_rd(ufc, 2^23)  -> floor(ufc) in mantissa low bits
//   kf  = y - 2^23 ; u = uf - kf
//   k   = (uf > 14) ? 14 : k0          (strict: uf==14 i.e. t==1 -> piece 12)
//   4 conflict-free LDS.32 + 3-FMA Horner; affine part folded into c0,c1.
// ---------------------------------------------------------------------------
__device__ __forceinline__ float eval_one(float x, float av2, float bv2,
                                          const float* tab) {
    const float MAGIC = 8388608.0f;            // 2^23
    float uf  = fmaf(x, av2, bv2);
    float ufc = fminf(fmaxf(uf, 0.0f), 13.0f);
    float y   = __fadd_rd(ufc, MAGIC);
    int   k0  = __float_as_int(y) & 15;        // 0..13
    float kf  = y - MAGIC;                     // exact float floor
    float u   = uf - kf;
    int k = (uf > 14.0f) ? 14 : k0;
    float c0 = tab[k];
    float c1 = tab[16 + k];
    float c2 = tab[32 + k];
    float c3 = tab[48 + k];
    float p = fmaf(c3, u, c2);
    p = fmaf(p, u, c1);
    return fmaf(p, u, c0);
}

// ---------------------------------------------------------------------------
// grid = 2048 blocks (1 per (b,c) plane), block = 256, 4 float4 per thread.
// (Proven best amortization of table build; regs=32, occ ~80%.)
// ---------------------------------------------------------------------------
__global__ void __launch_bounds__(256)
kan_spline_fused(const float4* __restrict__ x,
                 const float*  __restrict__ a,
                 const float*  __restrict__ b,
                 const float*  __restrict__ alpha,
                 const float*  __restrict__ gain,
                 const float*  __restrict__ bias,
                 float4* __restrict__ out) {
    __shared__ float tab[64];              // [power*16 + k], conflict-free

    int bid = blockIdx.x;
    int c = bid & (Cn - 1);
    int tid = threadIdx.x;

    if (tid < 15) {
        float av = a[c];
        float bv = b[c];
        float gv = gain[c];
        float bi = bias[c];
        // affine fold: gv*x + bi = g1*u + g0  with u = uf - keff
        float g1 = gv / (6.5f * av);
        float keff = (float)min(tid, 13);  // entry 14 uses u from kf=13
        float g0 = fmaf(g1, keff - 7.5f - 6.5f * bv, bi);

        float c0 = g0, c1 = g1, c2 = 0.0f, c3 = 0.0f;
        int sr = tid - 1;                  // -1..13 ; valid pieces 0..12
        if (sr >= 0 && sr <= 12) {
            float al0 = alpha[c * Kn + sr];
            float al1 = alpha[c * Kn + sr + 1];
            float al2 = alpha[c * Kn + sr + 2];
            float al3 = alpha[c * Kn + sr + 3];
            const float (*M)[4] = c_tab.m[sr];
            c0 += fmaf(M[0][0], al0, fmaf(M[0][1], al1, fmaf(M[0][2], al2, M[0][3] * al3)));
            c1 += fmaf(M[1][0], al0, fmaf(M[1][1], al1, fmaf(M[1][2], al2, M[1][3] * al3)));
            c2  = fmaf(M[2][0], al0, fmaf(M[2][1], al1, fmaf(M[2][2], al2, M[2][3] * al3)));
            c3  = fmaf(M[3][0], al0, fmaf(M[3][1], al1, fmaf(M[3][2], al2, M[3][3] * al3)));
        }
        tab[tid]      = c0;
        tab[16 + tid] = c1;
        tab[32 + tid] = c2;
        tab[48 + tid] = c3;
    }
    float av2 = 6.5f * __ldg(a + c);                 // uf = x*(6.5a) + (6.5b+7.5)
    float bv2 = fmaf(6.5f, __ldg(b + c), 7.5f);
    __syncthreads();

    // 4 float4 per thread: block covers one 1024-float4 plane
    int base = bid * 1024 + tid;
    float4 x0 = __ldg(x + base);
    float4 x1 = __ldg(x + base + 256);
    float4 x2 = __ldg(x + base + 512);
    float4 x3 = __ldg(x + base + 768);

    float4 o0, o1, o2, o3;
    o0.x = eval_one(x0.x, av2, bv2, tab);
    o0.y = eval_one(x0.y, av2, bv2, tab);
    o0.z = eval_one(x0.z, av2, bv2, tab);
    o0.w = eval_one(x0.w, av2, bv2, tab);
    o1.x = eval_one(x1.x, av2, bv2, tab);
    o1.y = eval_one(x1.y, av2, bv2, tab);
    o1.z = eval_one(x1.z, av2, bv2, tab);
    o1.w = eval_one(x1.w, av2, bv2, tab);
    o2.x = eval_one(x2.x, av2, bv2, tab);
    o2.y = eval_one(x2.y, av2, bv2, tab);
    o2.z = eval_one(x2.z, av2, bv2, tab);
    o2.w = eval_one(x2.w, av2, bv2, tab);
    o3.x = eval_one(x3.x, av2, bv2, tab);
    o3.y = eval_one(x3.y, av2, bv2, tab);
    o3.z = eval_one(x3.z, av2, bv2, tab);
    o3.w = eval_one(x3.w, av2, bv2, tab);

    out[base]       = o0;
    out[base + 256] = o1;
    out[base + 512] = o2;
    out[base + 768] = o3;
}

// ---------------------------------------------------------------------------
// Launch: d_in order = x, a, b, alpha, id_gain, bias
// ---------------------------------------------------------------------------
extern "C" void kernel_launch(void* const* d_in, const int* in_sizes, int n_in,
                              void* d_out, int out_size) {
    const float* x      = (const float*)d_in[0];
    const float* a      = (const float*)d_in[1];
    const float* b      = (const float*)d_in[2];
    const float* alpha  = (const float*)d_in[3];
    const float* gain   = (const float*)d_in[4];
    const float* bias   = (const float*)d_in[5];
    float* out = (float*)d_out;

    const int blocks = Bn * Cn;                   // 2048 planes
    kan_spline_fused<<<blocks, 256>>>((const float4*)x, a, b, alpha, gain, bias,
                                      (float4*)out);
}

// round 10
// speedup vs baseline: 1.4645x; 1.1516x over previous
#include <cuda_runtime.h>

// Problem constants (fixed by the dataset)
#define Bn 16
#define Cn 128
#define Hn 64
#define Wn 64
#define Kn 16

// ---------------------------------------------------------------------------
// Compile-time: per-piece 4x4 matrices M[sr][m][j] = monomial coeff m (of u in
// [0,1]) of basis function alpha_{sr+j}'s polynomial on piece sr.
// ---------------------------------------------------------------------------
constexpr double kn_c(int i) {
    return i <= 3 ? -1.0 : (i >= 16 ? 1.0 : -1.0 + (double)(i - 3) * (2.0 / 13.0));
}

struct B4 { double n[4]; };

constexpr B4 basis_at(double tt, int sr) {
    const int span = sr + 3;
    double lft[4] = {0, 0, 0, 0}, rgt[4] = {0, 0, 0, 0}, Nb[4] = {1.0, 0, 0, 0};
    for (int j = 1; j <= 3; j++) {
        lft[j] = tt - kn_c(span + 1 - j);
        rgt[j] = kn_c(span + j) - tt;
        double saved = 0.0;
        for (int r = 0; r < j; r++) {
            double den = rgt[r + 1] + lft[j - r];
            double tmp = Nb[r] / den;
            Nb[r] = saved + rgt[r + 1] * tmp;
            saved = lft[j - r] * tmp;
        }
        Nb[j] = saved;
    }
    B4 b = {{Nb[0], Nb[1], Nb[2], Nb[3]}};
    return b;
}

struct Tab { float m[13][4][4]; };   // [piece][monomial power][alpha j]

constexpr Tab make_tab() {
    Tab T = {};
    const double h = 2.0 / 13.0;
    for (int sr = 0; sr < 13; sr++) {
        double t0 = -1.0 + (double)sr * h;
        for (int j = 0; j < 4; j++) {
            double y0 = basis_at(t0, sr).n[j];
            double y1 = basis_at(t0 + h / 3.0, sr).n[j];
            double y2 = basis_at(t0 + 2.0 * h / 3.0, sr).n[j];
            double y3 = basis_at(t0 + h, sr).n[j];
            double d0 = y0;
            double d1 = 3.0 * (y1 - y0);
            double d2 = 4.5 * (y2 - 2.0 * y1 + y0);
            double d3 = 4.5 * (y3 - 3.0 * y2 + 3.0 * y1 - y0);
            T.m[sr][0][j] = (float)d0;
            T.m[sr][1][j] = (float)(d1 - d2 / 3.0 + 2.0 * d3 / 9.0);
            T.m[sr][2][j] = (float)(d2 - d3);
            T.m[sr][3][j] = (float)d3;
        }
    }
    return T;
}

__constant__ Tab c_tab = make_tab();

// ---------------------------------------------------------------------------
// Per-element (all 4-cycle FMA/ALU ops in the dependent chain):
//   uf  = x*av2 + bv2 ;  ufc = clamp(uf, 0, 13)
//   y   = fadd_rd(ufc, 2^23) -> floor in mantissa ; kf = y - 2^23 ; u = uf-kf
//   k   = (uf > 14) ? 14 : k0        (strict: uf==14 i.e. t==1 -> piece 12)
//   4 conflict-free LDS.32 + 3-FMA Horner; affine part folded into c0,c1.
// ---------------------------------------------------------------------------
__device__ __forceinline__ float eval_one(float x, float av2, float bv2,
                                          const float* tab) {
    const float MAGIC = 8388608.0f;            // 2^23
    float uf  = fmaf(x, av2, bv2);
    float ufc = fminf(fmaxf(uf, 0.0f), 13.0f);
    float y   = __fadd_rd(ufc, MAGIC);
    int   k0  = __float_as_int(y) & 15;        // 0..13
    float kf  = y - MAGIC;                     // exact float floor
    float u   = uf - kf;
    int k = (uf > 14.0f) ? 14 : k0;
    float c0 = tab[k];
    float c1 = tab[16 + k];
    float c2 = tab[32 + k];
    float c3 = tab[48 + k];
    float p = fmaf(c3, u, c2);
    p = fmaf(p, u, c1);
    return fmaf(p, u, c0);
}

__device__ __forceinline__ void do_plane4(const float4* __restrict__ x,
                                          float4* __restrict__ out,
                                          int base, float av2, float bv2,
                                          const float* tab) {
    float4 x0 = __ldg(x + base);
    float4 x1 = __ldg(x + base + 256);
    float4 x2 = __ldg(x + base + 512);
    float4 x3 = __ldg(x + base + 768);

    float4 o0, o1, o2, o3;
    o0.x = eval_one(x0.x, av2, bv2, tab);
    o0.y = eval_one(x0.y, av2, bv2, tab);
    o0.z = eval_one(x0.z, av2, bv2, tab);
    o0.w = eval_one(x0.w, av2, bv2, tab);
    o1.x = eval_one(x1.x, av2, bv2, tab);
    o1.y = eval_one(x1.y, av2, bv2, tab);
    o1.z = eval_one(x1.z, av2, bv2, tab);
    o1.w = eval_one(x1.w, av2, bv2, tab);
    o2.x = eval_one(x2.x, av2, bv2, tab);
    o2.y = eval_one(x2.y, av2, bv2, tab);
    o2.z = eval_one(x2.z, av2, bv2, tab);
    o2.w = eval_one(x2.w, av2, bv2, tab);
    o3.x = eval_one(x3.x, av2, bv2, tab);
    o3.y = eval_one(x3.y, av2, bv2, tab);
    o3.z = eval_one(x3.z, av2, bv2, tab);
    o3.w = eval_one(x3.w, av2, bv2, tab);

    out[base]       = o0;
    out[base + 256] = o1;
    out[base + 512] = o2;
    out[base + 768] = o3;
}

// ---------------------------------------------------------------------------
// grid = 1024 blocks (SINGLE WAVE at occ 8; 148*8 = 1184 >= 1024), block = 256.
// Block bid handles plane bid AND plane bid+1024 — same channel (bid & 127 ==
// (bid+1024) & 127), so ONE table build serves 2048 float4 of work.
// ---------------------------------------------------------------------------
__global__ void __launch_bounds__(256)
kan_spline_fused(const float4* __restrict__ x,
                 const float*  __restrict__ a,
                 const float*  __restrict__ b,
                 const float*  __restrict__ alpha,
                 const float*  __restrict__ gain,
                 const float*  __restrict__ bias,
                 float4* __restrict__ out) {
    __shared__ float tab[64];              // [power*16 + k], conflict-free

    int bid = blockIdx.x;
    int c = bid & (Cn - 1);
    int tid = threadIdx.x;

    if (tid < 15) {
        float av = a[c];
        float bv = b[c];
        float gv = gain[c];
        float bi = bias[c];
        // affine fold: gv*x + bi = g1*u + g0  with u = uf - keff
        float g1 = gv / (6.5f * av);
        float keff = (float)min(tid, 13);  // entry 14 uses u from kf=13
        float g0 = fmaf(g1, keff - 7.5f - 6.5f * bv, bi);

        float c0 = g0, c1 = g1, c2 = 0.0f, c3 = 0.0f;
        int sr = tid - 1;                  // -1..13 ; valid pieces 0..12
        if (sr >= 0 && sr <= 12) {
            float al0 = alpha[c * Kn + sr];
            float al1 = alpha[c * Kn + sr + 1];
            float al2 = alpha[c * Kn + sr + 2];
            float al3 = alpha[c * Kn + sr + 3];
            const float (*M)[4] = c_tab.m[sr];
            c0 += fmaf(M[0][0], al0, fmaf(M[0][1], al1, fmaf(M[0][2], al2, M[0][3] * al3)));
            c1 += fmaf(M[1][0], al0, fmaf(M[1][1], al1, fmaf(M[1][2], al2, M[1][3] * al3)));
            c2  = fmaf(M[2][0], al0, fmaf(M[2][1], al1, fmaf(M[2][2], al2, M[2][3] * al3)));
            c3  = fmaf(M[3][0], al0, fmaf(M[3][1], al1, fmaf(M[3][2], al2, M[3][3] * al3)));
        }
        tab[tid]      = c0;
        tab[16 + tid] = c1;
        tab[32 + tid] = c2;
        tab[48 + tid] = c3;
    }
    float av2 = 6.5f * __ldg(a + c);                 // uf = x*(6.5a) + (6.5b+7.5)
    float bv2 = fmaf(6.5f, __ldg(b + c), 7.5f);
    __syncthreads();

    // plane bid, then plane bid+1024 (same channel). Two groups of 4 float4
    // keep register pressure at the proven ~32-reg level.
    int base0 = bid * 1024 + tid;
    do_plane4(x, out, base0, av2, bv2, tab);
    do_plane4(x, out, base0 + 1024 * 1024, av2, bv2, tab);
}

// ---------------------------------------------------------------------------
// Launch: d_in order = x, a, b, alpha, id_gain, bias
// ---------------------------------------------------------------------------
extern "C" void kernel_launch(void* const* d_in, const int* in_sizes, int n_in,
                              void* d_out, int out_size) {
    const float* x      = (const float*)d_in[0];
    const float* a      = (const float*)d_in[1];
    const float* b      = (const float*)d_in[2];
    const float* alpha  = (const float*)d_in[3];
    const float* gain   = (const float*)d_in[4];
    const float* bias   = (const float*)d_in[5];
    float* out = (float*)d_out;

    const int blocks = 1024;   // single wave; each block does 2 planes
    kan_spline_fused<<<blocks, 256>>>((const float4*)x, a, b, alpha, gain, bias,
                                      (float4*)out);
}